// round 3
// baseline (speedup 1.0000x reference)
#include <cuda_runtime.h>

#define BB 8
#define NSEQ 256
#define DD 300
#define PPROJ 128
#define MROWS (BB*NSEQ)          // 2048
#define FEATW 512                // left | right | hs | he

// Scratch: [row][0:128 left | 128:256 right | 256:384 hs | 384:512 he]
__device__ float g_feat[MROWS * FEATW];

// ---------------------------------------------------------------------------
// Kernel 1: fused gather + GEMM  [2048 x 300] @ [300 x 512]
// grid (32 Mtiles, 8 Ntiles), 256 threads, BM=BN=64, BK=30 (300 = 10*30 exact)
// ---------------------------------------------------------------------------
__global__ __launch_bounds__(256) void gemm_kernel(
    const int*   __restrict__ sent, const float* __restrict__ emb,
    const float* __restrict__ Wl,   const float* __restrict__ bl,
    const float* __restrict__ Wr,
    const float* __restrict__ Ws1,  const float* __restrict__ bs1,
    const float* __restrict__ We1,  const float* __restrict__ be1)
{
    const int BM = 64, BN = 64, BK = 30, PAD = 68;   // 68*4B = 272B, 16B aligned rows
    __shared__ float As[BK * PAD];
    __shared__ float Bs[BK * PAD];
    __shared__ int   rowidx[BM];

    const int m0  = blockIdx.x * BM;
    const int n0  = blockIdx.y * BN;       // 0..511
    const int seg = n0 >> 7;               // 0:left 1:right 2:hs 3:he
    const int nl0 = n0 & 127;              // column within the segment's W

    const float* W;
    const float* bias = nullptr;
    bool relu = false;
    if      (seg == 0) { W = Wl;  bias = bl;  }
    else if (seg == 1) { W = Wr;              }
    else if (seg == 2) { W = Ws1; bias = bs1; relu = true; }
    else               { W = We1; bias = be1; relu = true; }

    const int tid = threadIdx.x;
    if (tid < BM) rowidx[tid] = sent[m0 + tid];
    __syncthreads();

    const int tx = tid & 15;   // 0..15 -> 4 output cols
    const int ty = tid >> 4;   // 0..15 -> 4 output rows
    float acc[4][4] = {};

    for (int k0 = 0; k0 < DD; k0 += BK) {
        // A tile: gathered embedding rows, k-fast coalesced reads
        for (int idx = tid; idx < BM * BK; idx += 256) {
            int m = idx / BK, k = idx % BK;
            As[k * PAD + m] = emb[(long)rowidx[m] * DD + k0 + k];
        }
        // B tile: W is [128,300] row-major, we need B[k][n] = W[n][k]
        for (int idx = tid; idx < BN * BK; idx += 256) {
            int n = idx / BK, k = idx % BK;
            Bs[k * PAD + n] = W[(nl0 + n) * DD + k0 + k];
        }
        __syncthreads();
        #pragma unroll
        for (int k = 0; k < BK; k++) {
            float4 a = *(const float4*)&As[k * PAD + ty * 4];
            float4 b = *(const float4*)&Bs[k * PAD + tx * 4];
            float av[4] = {a.x, a.y, a.z, a.w};
            float bv[4] = {b.x, b.y, b.z, b.w};
            #pragma unroll
            for (int i = 0; i < 4; i++)
                #pragma unroll
                for (int j = 0; j < 4; j++)
                    acc[i][j] += av[i] * bv[j];
        }
        __syncthreads();
    }

    #pragma unroll
    for (int i = 0; i < 4; i++) {
        const int m = m0 + ty * 4 + i;
        #pragma unroll
        for (int j = 0; j < 4; j++) {
            const int nl = tx * 4 + j;
            float v = acc[i][j];
            if (bias) v += bias[nl0 + nl];
            if (relu) v = fmaxf(v, 0.f);
            g_feat[m * FEATW + n0 + nl] = v;
        }
    }
}

// ---------------------------------------------------------------------------
// Kernel 2: start/end heads. One warp per row. grid 256 x 256 thr = 2048 warps.
// ---------------------------------------------------------------------------
__global__ __launch_bounds__(256) void startend_kernel(
    const float* __restrict__ Ws2, const float* __restrict__ bs2,
    const float* __restrict__ We2, const float* __restrict__ be2,
    float* __restrict__ out)
{
    const int warp = blockIdx.x * 8 + (threadIdx.x >> 5);
    const int lane = threadIdx.x & 31;
    const float* hs = &g_feat[warp * FEATW + 256];
    const float* he = &g_feat[warp * FEATW + 384];
    float s = 0.f, e = 0.f;
    #pragma unroll
    for (int u = 0; u < 4; u++) {
        const int p = lane + u * 32;
        s += hs[p] * Ws2[p];
        e += he[p] * We2[p];
    }
    #pragma unroll
    for (int o = 16; o; o >>= 1) {
        s += __shfl_xor_sync(0xFFFFFFFFu, s, o);
        e += __shfl_xor_sync(0xFFFFFFFFu, e, o);
    }
    if (lane == 0) {
        out[BB * NSEQ * NSEQ + warp]         = s + bs2[0];
        out[BB * NSEQ * NSEQ + MROWS + warp] = e + be2[0];
    }
}

// ---------------------------------------------------------------------------
// Kernel 3: bigram = relu(left[b,j,:] + right[b,i,:]) . Wo + bo
// grid (jtiles=8, itiles=8, B=8), 256 threads, tile = 32j x 32i,
// each thread: j = lane, ig = warp, 4 i-accumulators.
// LPAD=132 -> conflict-free float4 LDS across lanes; R/Wo reads broadcast.
// ---------------------------------------------------------------------------
__global__ __launch_bounds__(256) void bigram_kernel(
    const float* __restrict__ Wo, const float* __restrict__ bo,
    float* __restrict__ out)
{
    const int LPAD = 132;
    __shared__ float Ls[32 * LPAD];
    __shared__ float Rs[32 * LPAD];
    __shared__ float wos[128];

    const int b  = blockIdx.z;
    const int i0 = blockIdx.y * 32;
    const int j0 = blockIdx.x * 32;
    const int tid = threadIdx.x;

    // Stage L tile (32 x 128 floats as float4)
    for (int idx = tid; idx < 32 * 32; idx += 256) {
        const int r = idx >> 5, c4 = idx & 31;
        float4 v = *(const float4*)&g_feat[(b * NSEQ + j0 + r) * FEATW + c4 * 4];
        *(float4*)&Ls[r * LPAD + c4 * 4] = v;
    }
    // Stage R tile
    for (int idx = tid; idx < 32 * 32; idx += 256) {
        const int r = idx >> 5, c4 = idx & 31;
        float4 v = *(const float4*)&g_feat[(b * NSEQ + i0 + r) * FEATW + 128 + c4 * 4];
        *(float4*)&Rs[r * LPAD + c4 * 4] = v;
    }
    if (tid < 128) wos[tid] = Wo[tid];
    __syncthreads();

    const int j  = tid & 31;    // lane
    const int ig = tid >> 5;    // warp -> i-group of 4
    float acc[4] = {};
    const float* lrow  = &Ls[j * LPAD];
    const float* rbase = &Rs[(ig * 4) * LPAD];

    #pragma unroll 8
    for (int p = 0; p < 128; p += 4) {
        const float4 l4 = *(const float4*)&lrow[p];
        const float4 w4 = *(const float4*)&wos[p];
        #pragma unroll
        for (int ii = 0; ii < 4; ii++) {
            const float4 r4 = *(const float4*)&rbase[ii * LPAD + p];
            acc[ii] += fmaxf(l4.x + r4.x, 0.f) * w4.x;
            acc[ii] += fmaxf(l4.y + r4.y, 0.f) * w4.y;
            acc[ii] += fmaxf(l4.z + r4.z, 0.f) * w4.z;
            acc[ii] += fmaxf(l4.w + r4.w, 0.f) * w4.w;
        }
    }

    const float bov = bo[0];
    #pragma unroll
    for (int ii = 0; ii < 4; ii++) {
        const int i = i0 + ig * 4 + ii;
        out[(b * NSEQ + i) * NSEQ + j0 + j] = acc[ii] + bov;
    }
}

// ---------------------------------------------------------------------------
extern "C" void kernel_launch(void* const* d_in, const int* in_sizes, int n_in,
                              void* d_out, int out_size)
{
    const int*   sent = (const int*)  d_in[0];
    const float* emb  = (const float*)d_in[1];
    const float* Wl   = (const float*)d_in[2];
    const float* bl   = (const float*)d_in[3];
    const float* Wr   = (const float*)d_in[4];
    const float* Wo   = (const float*)d_in[5];
    const float* bo   = (const float*)d_in[6];
    const float* Ws1  = (const float*)d_in[7];
    const float* bs1  = (const float*)d_in[8];
    const float* Ws2  = (const float*)d_in[9];
    const float* bs2  = (const float*)d_in[10];
    const float* We1  = (const float*)d_in[11];
    const float* be1  = (const float*)d_in[12];
    const float* We2  = (const float*)d_in[13];
    const float* be2  = (const float*)d_in[14];
    float* out = (float*)d_out;

    dim3 ggrid(32, 8);
    gemm_kernel<<<ggrid, 256>>>(sent, emb, Wl, bl, Wr, Ws1, bs1, We1, be1);

    startend_kernel<<<256, 256>>>(Ws2, bs2, We2, be2, out);

    dim3 bgrid(8, 8, 8);
    bigram_kernel<<<bgrid, 256>>>(Wo, bo, out);
}

// round 5
// speedup vs baseline: 1.2301x; 1.2301x over previous
#include <cuda_runtime.h>

#define BB 8
#define NSEQ 256
#define DD 300
#define MROWS (BB*NSEQ)          // 2048
#define FEATW 512                // left | right | hs | he

typedef unsigned long long ull;

// Scratch: [row][0:128 left | 128:256 right | 256:384 hs | 384:512 he]
__device__ float g_feat[MROWS * FEATW];

// ---- packed f32x2 helpers (sm_100+) --------------------------------------
__device__ __forceinline__ ull f2_pack(float x, float y) {
    ull r; asm("mov.b64 %0, {%1,%2};" : "=l"(r) : "f"(x), "f"(y)); return r;
}
__device__ __forceinline__ float2 f2_unpack(ull v) {
    float2 r; asm("mov.b64 {%0,%1}, %2;" : "=f"(r.x), "=f"(r.y) : "l"(v)); return r;
}
#define FMA2(d,a,b,c) asm("fma.rn.f32x2 %0, %1, %2, %3;" : "=l"(d) : "l"(a), "l"(b), "l"(c))
#define ADD2(d,a,b)   asm("add.rn.f32x2 %0, %1, %2;"     : "=l"(d) : "l"(a), "l"(b))

// ---------------------------------------------------------------------------
// Kernel 1: fused gather + GEMM  [2048 x 300] @ [300 x 512]
// grid (16 Mtiles, 8 Ntiles), 256 threads. BM=128, BN=64, BK=30 (300=10*30).
// 8x8 per-thread microtile as 8 x (2 f32x2 pairs); register double-buffered
// tile staging; one __syncthreads per K-tile.
// ---------------------------------------------------------------------------
__global__ __launch_bounds__(256) void gemm_kernel(
    const int*   __restrict__ sent, const float* __restrict__ emb,
    const float* __restrict__ Wl,   const float* __restrict__ bl,
    const float* __restrict__ Wr,
    const float* __restrict__ Ws1,  const float* __restrict__ bs1,
    const float* __restrict__ We1,  const float* __restrict__ be1)
{
    const int BK = 30, PADA = 136, PADB = 72;
    __shared__ __align__(16) float As[2][BK * PADA];
    __shared__ __align__(16) float Bs[2][BK * PADB];
    __shared__ int rowidx[128];

    const int m0  = blockIdx.x * 128;
    const int n0  = blockIdx.y * 64;
    const int seg = n0 >> 7;            // 0:left 1:right 2:hs 3:he
    const int nl0 = n0 & 127;

    const float* W; const float* bias = nullptr; bool relu = false;
    if      (seg == 0) { W = Wl;  bias = bl;  }
    else if (seg == 1) { W = Wr;              }
    else if (seg == 2) { W = Ws1; bias = bs1; relu = true; }
    else               { W = We1; bias = be1; relu = true; }

    const int tid = threadIdx.x;
    if (tid < 128) rowidx[tid] = sent[m0 + tid];
    __syncthreads();

    // register prefetch buffers: A tile 128x30 = 3840 = 15*256, B tile 64x30 = 1920
    float aR[15], bR[8];
    #pragma unroll
    for (int i = 0; i < 15; i++) {
        int idx = i * 256 + tid; int m = idx / 30; int k = idx - m * 30;
        aR[i] = emb[(long)rowidx[m] * DD + k];
    }
    #pragma unroll
    for (int i = 0; i < 8; i++) {
        int idx = i * 256 + tid;
        if (idx < 1920) { int n = idx / 30; int k = idx - n * 30; bR[i] = W[(nl0 + n) * DD + k]; }
    }

    const int tx = tid & 15;   // 4 n-cols (2 f32x2 pairs)
    const int ty = tid >> 4;   // 8 m-rows
    ull acc[8][2];
    #pragma unroll
    for (int i = 0; i < 8; i++) { acc[i][0] = 0ull; acc[i][1] = 0ull; }

    for (int t = 0; t < 10; t++) {
        const int c = t & 1;
        // write prefetched regs -> smem buffer c
        #pragma unroll
        for (int i = 0; i < 15; i++) {
            int idx = i * 256 + tid; int m = idx / 30; int k = idx - m * 30;
            As[c][k * PADA + m] = aR[i];
        }
        #pragma unroll
        for (int i = 0; i < 8; i++) {
            int idx = i * 256 + tid;
            if (idx < 1920) { int n = idx / 30; int k = idx - n * 30; Bs[c][k * PADB + n] = bR[i]; }
        }
        __syncthreads();

        // issue global loads for next tile (latency hides under compute)
        if (t < 9) {
            const int k0 = (t + 1) * BK;
            #pragma unroll
            for (int i = 0; i < 15; i++) {
                int idx = i * 256 + tid; int m = idx / 30; int k = idx - m * 30;
                aR[i] = emb[(long)rowidx[m] * DD + k0 + k];
            }
            #pragma unroll
            for (int i = 0; i < 8; i++) {
                int idx = i * 256 + tid;
                if (idx < 1920) { int n = idx / 30; int k = idx - n * 30; bR[i] = W[(nl0 + n) * DD + k0 + k]; }
            }
        }

        #pragma unroll
        for (int k = 0; k < BK; k++) {
            const float4 a0 = *(const float4*)&As[c][k * PADA + ty * 8];
            const float4 a1 = *(const float4*)&As[c][k * PADA + ty * 8 + 4];
            const ull b0 = *(const ull*)&Bs[c][k * PADB + tx * 4];
            const ull b1 = *(const ull*)&Bs[c][k * PADB + tx * 4 + 2];
            const float av[8] = {a0.x, a0.y, a0.z, a0.w, a1.x, a1.y, a1.z, a1.w};
            #pragma unroll
            for (int i = 0; i < 8; i++) {
                const ull ap = f2_pack(av[i], av[i]);
                FMA2(acc[i][0], ap, b0, acc[i][0]);
                FMA2(acc[i][1], ap, b1, acc[i][1]);
            }
        }
        // no trailing sync: next iter writes the OTHER buffer; all warps that
        // could write buffer c again must first pass next iter's sync.
    }

    #pragma unroll
    for (int i = 0; i < 8; i++) {
        const int m = m0 + ty * 8 + i;
        #pragma unroll
        for (int jp = 0; jp < 2; jp++) {
            float2 v = f2_unpack(acc[i][jp]);
            const int nl = tx * 4 + jp * 2;
            if (bias) { v.x += bias[nl0 + nl]; v.y += bias[nl0 + nl + 1]; }
            if (relu) { v.x = fmaxf(v.x, 0.f); v.y = fmaxf(v.y, 0.f); }
            *(float2*)&g_feat[m * FEATW + n0 + nl] = v;
        }
    }
}

// ---------------------------------------------------------------------------
// Kernel 2: start/end heads. One warp per row.
// ---------------------------------------------------------------------------
__global__ __launch_bounds__(256) void startend_kernel(
    const float* __restrict__ Ws2, const float* __restrict__ bs2,
    const float* __restrict__ We2, const float* __restrict__ be2,
    float* __restrict__ out)
{
    const int warp = blockIdx.x * 8 + (threadIdx.x >> 5);
    const int lane = threadIdx.x & 31;
    const float* hs = &g_feat[warp * FEATW + 256];
    const float* he = &g_feat[warp * FEATW + 384];
    float s = 0.f, e = 0.f;
    #pragma unroll
    for (int u = 0; u < 4; u++) {
        const int p = lane + u * 32;
        s += hs[p] * Ws2[p];
        e += he[p] * We2[p];
    }
    #pragma unroll
    for (int o = 16; o; o >>= 1) {
        s += __shfl_xor_sync(0xFFFFFFFFu, s, o);
        e += __shfl_xor_sync(0xFFFFFFFFu, e, o);
    }
    if (lane == 0) {
        out[BB * NSEQ * NSEQ + warp]         = s + bs2[0];
        out[BB * NSEQ * NSEQ + MROWS + warp] = e + be2[0];
    }
}

// ---------------------------------------------------------------------------
// Kernel 3: bigram = relu(left[b,j,:] + right[b,i,:]) . Wo + bo
// 32j x 32i tile per block, j=lane, warp=4 i-rows; packed f32x2 along p.
// LPAD=130: lane-j LDS.64 at j*130+2q -> banks {2j, 2j+1}, conflict-free.
// R/Wo loads are warp-uniform -> broadcast.
// ---------------------------------------------------------------------------
__global__ __launch_bounds__(256) void bigram_kernel(
    const float* __restrict__ Wo, const float* __restrict__ bo,
    float* __restrict__ out)
{
    const int LPAD = 130;
    __shared__ __align__(16) float Ls[32 * LPAD];
    __shared__ __align__(16) float Rs[32 * LPAD];
    __shared__ __align__(16) float wos[128];

    const int b  = blockIdx.z;
    const int i0 = blockIdx.y * 32;
    const int j0 = blockIdx.x * 32;
    const int tid = threadIdx.x;

    for (int idx = tid; idx < 32 * 64; idx += 256) {
        const int r = idx >> 6, c2 = idx & 63;
        *(float2*)&Ls[r * LPAD + c2 * 2] =
            *(const float2*)&g_feat[(b * NSEQ + j0 + r) * FEATW + c2 * 2];
    }
    for (int idx = tid; idx < 32 * 64; idx += 256) {
        const int r = idx >> 6, c2 = idx & 63;
        *(float2*)&Rs[r * LPAD + c2 * 2] =
            *(const float2*)&g_feat[(b * NSEQ + i0 + r) * FEATW + 128 + c2 * 2];
    }
    if (tid < 128) wos[tid] = Wo[tid];
    __syncthreads();

    const int j  = tid & 31;
    const int ig = tid >> 5;
    ull acc[4] = {0ull, 0ull, 0ull, 0ull};
    const float* lrow = &Ls[j * LPAD];
    const float* rb   = &Rs[(ig * 4) * LPAD];

    #pragma unroll 16
    for (int q = 0; q < 64; q++) {
        const ull l = *(const ull*)&lrow[2 * q];
        const ull w = *(const ull*)&wos[2 * q];
        #pragma unroll
        for (int ii = 0; ii < 4; ii++) {
            const ull r = *(const ull*)&rb[ii * LPAD + 2 * q];
            ull s; ADD2(s, l, r);
            float2 sf = f2_unpack(s);
            sf.x = fmaxf(sf.x, 0.f);
            sf.y = fmaxf(sf.y, 0.f);
            FMA2(acc[ii], f2_pack(sf.x, sf.y), w, acc[ii]);
        }
    }

    const float bov = bo[0];
    #pragma unroll
    for (int ii = 0; ii < 4; ii++) {
        const float2 a = f2_unpack(acc[ii]);
        const int i = i0 + ig * 4 + ii;
        out[(b * NSEQ + i) * NSEQ + j0 + j] = a.x + a.y + bov;
    }
}

// ---------------------------------------------------------------------------
extern "C" void kernel_launch(void* const* d_in, const int* in_sizes, int n_in,
                              void* d_out, int out_size)
{
    const int*   sent = (const int*)  d_in[0];
    const float* emb  = (const float*)d_in[1];
    const float* Wl   = (const float*)d_in[2];
    const float* bl   = (const float*)d_in[3];
    const float* Wr   = (const float*)d_in[4];
    const float* Wo   = (const float*)d_in[5];
    const float* bo   = (const float*)d_in[6];
    const float* Ws1  = (const float*)d_in[7];
    const float* bs1  = (const float*)d_in[8];
    const float* Ws2  = (const float*)d_in[9];
    const float* bs2  = (const float*)d_in[10];
    const float* We1  = (const float*)d_in[11];
    const float* be1  = (const float*)d_in[12];
    const float* We2  = (const float*)d_in[13];
    const float* be2  = (const float*)d_in[14];
    float* out = (float*)d_out;

    dim3 ggrid(16, 8);
    gemm_kernel<<<ggrid, 256>>>(sent, emb, Wl, bl, Wr, Ws1, bs1, We1, be1);

    startend_kernel<<<256, 256>>>(Ws2, bs2, We2, be2, out);

    dim3 bgrid(8, 8, 8);
    bigram_kernel<<<bgrid, 256>>>(Wo, bo, out);
}

// round 6
// speedup vs baseline: 1.2699x; 1.0323x over previous
#include <cuda_runtime.h>

#define BB 8
#define NSEQ 256
#define DD 300
#define MROWS (BB*NSEQ)          // 2048
#define FEATW 512                // left | right | hs | he

typedef unsigned long long ull;

// Scratch: [row][0:128 left | 128:256 right | 256:384 hs | 384:512 he]
__device__ float g_feat[MROWS * FEATW];

// ---- packed f32x2 helpers (sm_100+) --------------------------------------
__device__ __forceinline__ ull f2_pack(float x, float y) {
    ull r; asm("mov.b64 %0, {%1,%2};" : "=l"(r) : "f"(x), "f"(y)); return r;
}
__device__ __forceinline__ float2 f2_unpack(ull v) {
    float2 r; asm("mov.b64 {%0,%1}, %2;" : "=f"(r.x), "=f"(r.y) : "l"(v)); return r;
}
#define FMA2(d,a,b,c) asm("fma.rn.f32x2 %0, %1, %2, %3;" : "=l"(d) : "l"(a), "l"(b), "l"(c))
#define ADD2(d,a,b)   asm("add.rn.f32x2 %0, %1, %2;"     : "=l"(d) : "l"(a), "l"(b))

// ---------------------------------------------------------------------------
// Kernel 1: fused gather + GEMM  [2048 x 300] @ [300 x 512]
// grid (16 Mtiles, 8 Ntiles), 256 threads. BM=128, BN=64, BK=20 (300=15*20).
// f32x2 pairs over M: A frag loads come pre-packed (LDS.64 of adjacent m);
// B stored DUPLICATED (b,b) in smem -> pre-packed warp-uniform broadcast loads.
// Warp w owns n-columns [8w, 8w+8); lane L owns m rows {2L,2L+1,64+2L,65+2L}.
// Inner loop per k: 2 LDS.64 + 4 bcast LDS.128 + 16 FFMA2, ZERO packs.
// ---------------------------------------------------------------------------
__global__ __launch_bounds__(256) void gemm_kernel(
    const int*   __restrict__ sent, const float* __restrict__ emb,
    const float* __restrict__ Wl,   const float* __restrict__ bl,
    const float* __restrict__ Wr,
    const float* __restrict__ Ws1,  const float* __restrict__ bs1,
    const float* __restrict__ We1,  const float* __restrict__ be1)
{
    const int BK = 20, PADA = 132, PADB = 132;
    __shared__ __align__(16) float As[2][BK * PADA];   // [k][m]          128 used
    __shared__ __align__(16) float Bs[2][BK * PADB];   // [k][2n dup]     128 used
    __shared__ int rowidx[128];

    const int m0  = blockIdx.x * 128;
    const int n0  = blockIdx.y * 64;
    const int seg = n0 >> 7;            // 0:left 1:right 2:hs 3:he
    const int nl0 = n0 & 127;

    const float* W; const float* bias = nullptr; bool relu = false;
    if      (seg == 0) { W = Wl;  bias = bl;  }
    else if (seg == 1) { W = Wr;              }
    else if (seg == 2) { W = Ws1; bias = bs1; relu = true; }
    else               { W = We1; bias = be1; relu = true; }

    const int tid = threadIdx.x;
    if (tid < 128) rowidx[tid] = sent[m0 + tid];
    __syncthreads();

    // register prefetch: A tile 128x20 = 2560 = 10*256, B tile 64x20 = 1280 = 5*256
    float aR[10], bR[5];
    #pragma unroll
    for (int i = 0; i < 10; i++) {
        int idx = i * 256 + tid; int m = idx / 20; int k = idx - m * 20;
        aR[i] = emb[(long)rowidx[m] * DD + k];
    }
    #pragma unroll
    for (int i = 0; i < 5; i++) {
        int idx = i * 256 + tid; int n = idx / 20; int k = idx - n * 20;
        bR[i] = W[(nl0 + n) * DD + k];
    }

    const int lane = tid & 31;
    const int wid  = tid >> 5;          // warp -> 8 n-columns
    ull acc0[8], acc1[8];
    #pragma unroll
    for (int i = 0; i < 8; i++) { acc0[i] = 0ull; acc1[i] = 0ull; }

    for (int t = 0; t < 15; t++) {
        const int c = t & 1;
        // write prefetched regs -> smem buffer c
        #pragma unroll
        for (int i = 0; i < 10; i++) {
            int idx = i * 256 + tid; int m = idx / 20; int k = idx - m * 20;
            As[c][k * PADA + m] = aR[i];
        }
        #pragma unroll
        for (int i = 0; i < 5; i++) {
            int idx = i * 256 + tid; int n = idx / 20; int k = idx - n * 20;
            *(ull*)&Bs[c][k * PADB + 2 * n] = f2_pack(bR[i], bR[i]);
        }
        __syncthreads();

        // prefetch next tile while computing on this one
        if (t < 14) {
            const int k0 = (t + 1) * BK;
            #pragma unroll
            for (int i = 0; i < 10; i++) {
                int idx = i * 256 + tid; int m = idx / 20; int k = idx - m * 20;
                aR[i] = emb[(long)rowidx[m] * DD + k0 + k];
            }
            #pragma unroll
            for (int i = 0; i < 5; i++) {
                int idx = i * 256 + tid; int n = idx / 20; int k = idx - n * 20;
                bR[i] = W[(nl0 + n) * DD + k0 + k];
            }
        }

        #pragma unroll
        for (int k = 0; k < BK; k++) {
            const ull a0 = *(const ull*)&As[c][k * PADA + 2 * lane];       // (m, m+1)
            const ull a1 = *(const ull*)&As[c][k * PADA + 64 + 2 * lane];
            const ull* bp = (const ull*)&Bs[c][k * PADB + 16 * wid];       // bcast, 16B aligned
            ull b[8];
            #pragma unroll
            for (int n = 0; n < 8; n++) b[n] = bp[n];
            #pragma unroll
            for (int n = 0; n < 8; n++) {
                FMA2(acc0[n], a0, b[n], acc0[n]);
                FMA2(acc1[n], a1, b[n], acc1[n]);
            }
        }
        // no trailing sync: next iter writes the OTHER buffer; every warp has
        // finished this buffer's compute before passing the next iter's sync.
    }

    // epilogue: bias / relu / store (each thread: 4 m rows x 8 n cols)
    float bv[8];
    #pragma unroll
    for (int n = 0; n < 8; n++) bv[n] = bias ? bias[nl0 + 8 * wid + n] : 0.f;

    #pragma unroll
    for (int half = 0; half < 2; half++) {
        const ull* ac = half ? acc1 : acc0;
        const int mbase = m0 + half * 64 + 2 * lane;
        float2 u[8];
        #pragma unroll
        for (int n = 0; n < 8; n++) {
            u[n] = f2_unpack(ac[n]);
            u[n].x += bv[n]; u[n].y += bv[n];
            if (relu) { u[n].x = fmaxf(u[n].x, 0.f); u[n].y = fmaxf(u[n].y, 0.f); }
        }
        float* o0 = &g_feat[(long)mbase * FEATW + n0 + 8 * wid];
        float* o1 = o0 + FEATW;
        *(float4*)&o0[0] = make_float4(u[0].x, u[1].x, u[2].x, u[3].x);
        *(float4*)&o0[4] = make_float4(u[4].x, u[5].x, u[6].x, u[7].x);
        *(float4*)&o1[0] = make_float4(u[0].y, u[1].y, u[2].y, u[3].y);
        *(float4*)&o1[4] = make_float4(u[4].y, u[5].y, u[6].y, u[7].y);
    }
}

// ---------------------------------------------------------------------------
// Kernel 2: start/end heads. One warp per row.
// ---------------------------------------------------------------------------
__global__ __launch_bounds__(256) void startend_kernel(
    const float* __restrict__ Ws2, const float* __restrict__ bs2,
    const float* __restrict__ We2, const float* __restrict__ be2,
    float* __restrict__ out)
{
    const int warp = blockIdx.x * 8 + (threadIdx.x >> 5);
    const int lane = threadIdx.x & 31;
    const float* hs = &g_feat[warp * FEATW + 256];
    const float* he = &g_feat[warp * FEATW + 384];
    float s = 0.f, e = 0.f;
    #pragma unroll
    for (int u = 0; u < 4; u++) {
        const int p = lane + u * 32;
        s += hs[p] * Ws2[p];
        e += he[p] * We2[p];
    }
    #pragma unroll
    for (int o = 16; o; o >>= 1) {
        s += __shfl_xor_sync(0xFFFFFFFFu, s, o);
        e += __shfl_xor_sync(0xFFFFFFFFu, e, o);
    }
    if (lane == 0) {
        out[BB * NSEQ * NSEQ + warp]         = s + bs2[0];
        out[BB * NSEQ * NSEQ + MROWS + warp] = e + be2[0];
    }
}

// ---------------------------------------------------------------------------
// Kernel 3: bigram = relu(left[b,j,:] + right[b,i,:]) . Wo + bo
// NEW decomposition: thread = one i (128 i per block), 16 j per block.
// right chunks live in REGISTERS (double-buffered global loads, L2-resident),
// left and Wo chunks are warp-uniform broadcast LDS -> tiny smem traffic.
// grid (16 jtiles, 2 itiles, 8 b), 128 threads.
// ---------------------------------------------------------------------------
__global__ __launch_bounds__(128) void bigram_kernel(
    const float* __restrict__ Wo, const float* __restrict__ bo,
    float* __restrict__ out)
{
    __shared__ __align__(16) float Ls[2176];   // 16 j x 128 p (2048) -> reused 128x17 transpose
    __shared__ __align__(16) float wos[128];

    const int b  = blockIdx.z;
    const int i0 = blockIdx.y * 128;
    const int j0 = blockIdx.x * 16;
    const int tid = threadIdx.x;

    // stage left tile [16 j][128 p]
    for (int idx = tid; idx < 512; idx += 128) {
        const int r = idx >> 5, c4 = idx & 31;
        *(float4*)&Ls[r * 128 + c4 * 4] =
            *(const float4*)&g_feat[(b * NSEQ + j0 + r) * FEATW + c4 * 4];
    }
    wos[tid] = Wo[tid];
    __syncthreads();

    const int i = i0 + tid;
    const float* rrow = &g_feat[(b * NSEQ + i) * FEATW + 128];

    ull acc[16];
    #pragma unroll
    for (int j = 0; j < 16; j++) acc[j] = 0ull;

    // right chunk double buffer (16 p per chunk = 4 float4 = 8 ull)
    float4 rc[4], rn[4];
    #pragma unroll
    for (int q = 0; q < 4; q++) rc[q] = *(const float4*)&rrow[q * 4];

    for (int pc = 0; pc < 8; pc++) {
        if (pc < 7) {
            #pragma unroll
            for (int q = 0; q < 4; q++) rn[q] = *(const float4*)&rrow[(pc + 1) * 16 + q * 4];
        }
        const ull* rv = (const ull*)rc;                      // 8 packed pairs
        const ull* wv = (const ull*)&wos[pc * 16];           // bcast
        const float* lbase = &Ls[pc * 16];

        #pragma unroll
        for (int up = 0; up < 4; up++) {                     // u-pair: 2 ull each
            const ull w0 = wv[2 * up], w1 = wv[2 * up + 1];
            const ull r0 = rv[2 * up], r1 = rv[2 * up + 1];
            #pragma unroll
            for (int j = 0; j < 16; j++) {                   // independent chains
                const ull* lp = (const ull*)&lbase[j * 128 + 4 * up];  // bcast LDS.128
                ull s0; ADD2(s0, lp[0], r0);
                float2 f0 = f2_unpack(s0);
                f0.x = fmaxf(f0.x, 0.f); f0.y = fmaxf(f0.y, 0.f);
                FMA2(acc[j], f2_pack(f0.x, f0.y), w0, acc[j]);
                ull s1; ADD2(s1, lp[1], r1);
                float2 f1 = f2_unpack(s1);
                f1.x = fmaxf(f1.x, 0.f); f1.y = fmaxf(f1.y, 0.f);
                FMA2(acc[j], f2_pack(f1.x, f1.y), w1, acc[j]);
            }
        }
        #pragma unroll
        for (int q = 0; q < 4; q++) rc[q] = rn[q];
    }

    // transpose through smem for coalesced output stores
    __syncthreads();                       // done reading Ls
    const float bov = bo[0];
    #pragma unroll
    for (int j = 0; j < 16; j++) {
        const float2 a = f2_unpack(acc[j]);
        Ls[tid * 17 + j] = a.x + a.y + bov;
    }
    __syncthreads();
    #pragma unroll
    for (int it = 0; it < 4; it++) {
        const int f4 = it * 128 + tid;
        const int r  = f4 >> 2;            // i-local row
        const int jj = (f4 & 3) * 4;
        float4 v = make_float4(Ls[r * 17 + jj], Ls[r * 17 + jj + 1],
                               Ls[r * 17 + jj + 2], Ls[r * 17 + jj + 3]);
        *(float4*)&out[(b * NSEQ + i0 + r) * NSEQ + j0 + jj] = v;
    }
}

// ---------------------------------------------------------------------------
extern "C" void kernel_launch(void* const* d_in, const int* in_sizes, int n_in,
                              void* d_out, int out_size)
{
    const int*   sent = (const int*)  d_in[0];
    const float* emb  = (const float*)d_in[1];
    const float* Wl   = (const float*)d_in[2];
    const float* bl   = (const float*)d_in[3];
    const float* Wr   = (const float*)d_in[4];
    const float* Wo   = (const float*)d_in[5];
    const float* bo   = (const float*)d_in[6];
    const float* Ws1  = (const float*)d_in[7];
    const float* bs1  = (const float*)d_in[8];
    const float* Ws2  = (const float*)d_in[9];
    const float* bs2  = (const float*)d_in[10];
    const float* We1  = (const float*)d_in[11];
    const float* be1  = (const float*)d_in[12];
    const float* We2  = (const float*)d_in[13];
    const float* be2  = (const float*)d_in[14];
    float* out = (float*)d_out;

    dim3 ggrid(16, 8);
    gemm_kernel<<<ggrid, 256>>>(sent, emb, Wl, bl, Wr, Ws1, bs1, We1, be1);

    startend_kernel<<<256, 256>>>(Ws2, bs2, We2, be2, out);

    dim3 bgrid(16, 2, 8);
    bigram_kernel<<<bgrid, 128>>>(Wo, bo, out);
}